// round 9
// baseline (speedup 1.0000x reference)
#include <cuda_runtime.h>

// RPE MHA, sm_100a. B=2, N=M=512, C=256, H=8, D=32.
// scores_p = embed . wq with wq = Wp-projected q (avoids projecting embed).
// R8: q.kT and out-projection both fused into k_fused -> 3 launches total.

#define SCALE_Q 0.17677669529663687f  // 32^-0.5, folded into q projection

__device__ float g_q[1024 * 256];
__device__ float g_k[1024 * 256];
__device__ float g_v[1024 * 256];
__device__ float g_wq[8 * 1024 * 256];     // [h][bn][c]

// ---------------------------------------------------------------------------
// 64x64 tiled fp32 GEMM, 256 threads, K-tile 16, register double-buffered.
// BT=false: C = A[m][k] @ B[k][n].  BT=true: C = A[m][k] @ B[n][k].
// ---------------------------------------------------------------------------
template <bool BT>
__device__ __forceinline__ void gemm_body(
    const float* __restrict__ A, int lda,
    const float* __restrict__ B, int ldb,
    float* __restrict__ C, int ldc,
    int N, int K, float scale, const float* __restrict__ bias)
{
    __shared__ float As[64][20];
    __shared__ float Bs[16][68];

    const int tid = threadIdx.x;
    const int m0 = blockIdx.x * 64;
    const int n0 = blockIdx.y * 64;
    const int lr = tid >> 2;
    const int lc = (tid & 3) << 2;
    const int bk = tid >> 4;
    const int bn_ = (tid & 15) << 2;
    const int ty = tid >> 4;
    const int tx = tid & 15;

    float acc[4][4];
#pragma unroll
    for (int i = 0; i < 4; i++)
#pragma unroll
        for (int j = 0; j < 4; j++) acc[i][j] = 0.0f;

    float4 a4 = *(const float4*)(A + (long)(m0 + lr) * lda + lc);
    float4 b4;
    if (BT) {
        b4 = *(const float4*)(B + (long)(n0 + lr) * ldb + lc);
    } else {
        b4 = make_float4(0.f, 0.f, 0.f, 0.f);
        if (n0 + bn_ < N)
            b4 = *(const float4*)(B + (long)bk * ldb + n0 + bn_);
    }

    for (int k0 = 0; k0 < K; k0 += 16) {
        *(float4*)&As[lr][lc] = a4;
        if (BT) {
            Bs[lc + 0][lr] = b4.x;
            Bs[lc + 1][lr] = b4.y;
            Bs[lc + 2][lr] = b4.z;
            Bs[lc + 3][lr] = b4.w;
        } else {
            *(float4*)&Bs[bk][bn_] = b4;
        }
        __syncthreads();

        if (k0 + 16 < K) {
            a4 = *(const float4*)(A + (long)(m0 + lr) * lda + k0 + 16 + lc);
            if (BT) {
                b4 = *(const float4*)(B + (long)(n0 + lr) * ldb + k0 + 16 + lc);
            } else {
                b4 = make_float4(0.f, 0.f, 0.f, 0.f);
                if (n0 + bn_ < N)
                    b4 = *(const float4*)(B + (long)(k0 + 16 + bk) * ldb + n0 + bn_);
            }
        }

#pragma unroll
        for (int kk = 0; kk < 16; kk++) {
            float a[4];
#pragma unroll
            for (int i = 0; i < 4; i++) a[i] = As[ty * 4 + i][kk];
            float4 bb = *(const float4*)&Bs[kk][tx * 4];
#pragma unroll
            for (int i = 0; i < 4; i++) {
                acc[i][0] += a[i] * bb.x;
                acc[i][1] += a[i] * bb.y;
                acc[i][2] += a[i] * bb.z;
                acc[i][3] += a[i] * bb.w;
            }
        }
        __syncthreads();
    }

#pragma unroll
    for (int i = 0; i < 4; i++) {
#pragma unroll
        for (int j = 0; j < 4; j++) {
            int nn = n0 + tx * 4 + j;
            if (nn < N) {
                float val = acc[i][j] * scale;
                if (bias) val += bias[nn];
                C[(long)(m0 + ty * 4 + i) * ldc + nn] = val;
            }
        }
    }
}

// q/k/v projections batched over grid.z
__global__ void __launch_bounds__(256) k_gemm_qkv(
    const float* Aq, const float* Ak, const float* Av,
    const float* Bq, const float* Bk, const float* Bv,
    float* Cq, float* Ck, float* Cv)
{
    int z = blockIdx.z;
    const float* A = (z == 0) ? Aq : (z == 1) ? Ak : Av;
    const float* B = (z == 0) ? Bq : (z == 1) ? Bk : Bv;
    float*       C = (z == 0) ? Cq : (z == 1) ? Ck : Cv;
    gemm_body<false>(A, 256, B, 256, C, 256, 256, 256,
                     (z == 0) ? SCALE_Q : 1.0f, nullptr);
}

// wq[h] = Q_h @ Wp_h^T  (z = h, M=1024, N=256, K=32)
__global__ void __launch_bounds__(256) k_gemm_wq(
    const float* __restrict__ q, const float* __restrict__ Wp,
    float* __restrict__ wqo)
{
    int h = blockIdx.z;
    gemm_body<true>(q + h * 32, 256,
                    Wp + h * 32, 256,
                    wqo + (long)h * 262144, 256,
                    256, 32, 1.0f, nullptr);
}

// ---------------------------------------------------------------------------
// Fused: scores_p + scores_e + softmax + attn@V + out-projection.
// CTA per (b,n), 256 threads. Warp w owns rows m in [64w, 64w+64) for the
// score phase, head w for softmax + PV; whole CTA does the out-projection.
// ---------------------------------------------------------------------------
__device__ __forceinline__ float reduce8(const float* a, int l)
{
    float r[4];
#pragma unroll
    for (int j = 0; j < 4; j++) {
        float send = (l & 1) ? a[j] : a[j + 4];
        float keep = (l & 1) ? a[j + 4] : a[j];
        r[j] = keep + __shfl_xor_sync(0xFFFFFFFFu, send, 1);
    }
    float r2[2];
#pragma unroll
    for (int j = 0; j < 2; j++) {
        float send = (l & 2) ? r[j] : r[j + 2];
        float keep = (l & 2) ? r[j + 2] : r[j];
        r2[j] = keep + __shfl_xor_sync(0xFFFFFFFFu, send, 2);
    }
    float send = (l & 4) ? r2[0] : r2[1];
    float keep = (l & 4) ? r2[1] : r2[0];
    float s = keep + __shfl_xor_sync(0xFFFFFFFFu, send, 4);
    s += __shfl_xor_sync(0xFFFFFFFFu, s, 8);
    s += __shfl_xor_sync(0xFFFFFFFFu, s, 16);
    return s;
}

__global__ void __launch_bounds__(256, 2) k_fused(
    const float* __restrict__ embed,  // [b][n][m][c]
    const float* __restrict__ wq,     // [h][bn][c]
    const float* __restrict__ qmat,   // [bn][c]       (scaled q)
    const float* __restrict__ kmat,   // [b*512+m][c]
    const float* __restrict__ vmat,   // [b*512+m][c]
    const float* __restrict__ Wout,   // [c][c']
    const float* __restrict__ bout,   // [c']
    float* __restrict__ out)          // [bn][c']
{
    __shared__ float S[8 * 520];      // [h][m], pitch 520
    __shared__ float hidS[256];

    const int n = blockIdx.x;
    const int b = blockIdx.y;
    const int t = threadIdx.x;
    const int w = t >> 5, l = t & 31;
    const long bn = (long)b * 512 + n;

    // per-lane wq slice: channels 4l..4l+3 and 128+4l..128+4l+3, 8 heads
    float4 wq0[8], wq1[8];
#pragma unroll
    for (int h = 0; h < 8; h++) {
        const float* wp = wq + ((long)h * 1024 + bn) * 256;
        wq0[h] = *(const float4*)(wp + 4 * l);
        wq1[h] = *(const float4*)(wp + 128 + 4 * l);
    }
    // per-lane q slice (for the fused q.kT term)
    float4 qv0 = *(const float4*)(qmat + bn * 256 + 4 * l);
    float4 qv1 = *(const float4*)(qmat + bn * 256 + 128 + 4 * l);
    // head-select masks: lane's low channels belong to head l>>3,
    // high channels to head 4+(l>>3)
    float mk[4];
#pragma unroll
    for (int h = 0; h < 4; h++) mk[h] = (h == (l >> 3)) ? 1.0f : 0.0f;

    const int hlane = ((l & 1) << 2) | (l & 2) | ((l & 4) >> 2);

    const float4* E  = (const float4*)(embed + bn * 131072L) + (long)(w << 6) * 64;
    const float4* Kb = (const float4*)(kmat + (long)b * 131072) + (long)(w << 6) * 64;

    // prime prefetch: 2 embed rows
    float4 p0 = E[l], p1 = E[32 + l], p2 = E[64 + l], p3 = E[96 + l];

    for (int i = 0; i < 64; i += 2) {
        // k rows for this pair (L2-resident; issue early)
        const float4* Kr = Kb + i * 64;
        float4 ka0 = Kr[l], ka1 = Kr[32 + l];
        float4 kb0 = Kr[64 + l], kb1 = Kr[96 + l];

        float4 x0 = p0, x1 = p1, y0 = p2, y1 = p3;
        if (i + 2 < 64) {
            const float4* En = E + (i + 2) * 64;
            p0 = En[l]; p1 = En[32 + l]; p2 = En[64 + l]; p3 = En[96 + l];
        }

        float a[8], c[8];
#pragma unroll
        for (int h = 0; h < 8; h++) {
            a[h] = x0.x * wq0[h].x + x0.y * wq0[h].y
                 + x0.z * wq0[h].z + x0.w * wq0[h].w
                 + x1.x * wq1[h].x + x1.y * wq1[h].y
                 + x1.z * wq1[h].z + x1.w * wq1[h].w;
            c[h] = y0.x * wq0[h].x + y0.y * wq0[h].y
                 + y0.z * wq0[h].z + y0.w * wq0[h].w
                 + y1.x * wq1[h].x + y1.y * wq1[h].y
                 + y1.z * wq1[h].z + y1.w * wq1[h].w;
        }

        // q.kT contribution (scores_e), injected via 0/1 mask FFMAs
        float keA0 = ka0.x * qv0.x + ka0.y * qv0.y + ka0.z * qv0.z + ka0.w * qv0.w;
        float keA1 = ka1.x * qv1.x + ka1.y * qv1.y + ka1.z * qv1.z + ka1.w * qv1.w;
        float keB0 = kb0.x * qv0.x + kb0.y * qv0.y + kb0.z * qv0.z + kb0.w * qv0.w;
        float keB1 = kb1.x * qv1.x + kb1.y * qv1.y + kb1.z * qv1.z + kb1.w * qv1.w;
#pragma unroll
        for (int h = 0; h < 4; h++) {
            a[h]     += mk[h] * keA0;
            a[h + 4] += mk[h] * keA1;
            c[h]     += mk[h] * keB0;
            c[h + 4] += mk[h] * keB1;
        }

        float sA = reduce8(a, l);
        float sB = reduce8(c, l);
        if (l < 8) {
            S[hlane * 520 + (w << 6) + i]     = sA;
            S[hlane * 520 + (w << 6) + i + 1] = sB;
        }
    }
    __syncthreads();

    // softmax: warp w -> head w; lane owns m = {64j + 2l, +1}, j = 0..7
    const float* Sr = S + w * 520;
    float v[16];
    float mx = -3.0e38f;
#pragma unroll
    for (int j = 0; j < 8; j++) {
        float2 sv = *(const float2*)(Sr + j * 64 + l * 2);
        v[2 * j]     = sv.x;
        v[2 * j + 1] = sv.y;
        mx = fmaxf(mx, fmaxf(v[2 * j], v[2 * j + 1]));
    }
#pragma unroll
    for (int off = 16; off > 0; off >>= 1)
        mx = fmaxf(mx, __shfl_xor_sync(0xFFFFFFFFu, mx, off));

    float sum = 0.f;
#pragma unroll
    for (int j = 0; j < 16; j++) {
        v[j] = __expf(v[j] - mx);
        sum += v[j];
    }
#pragma unroll
    for (int off = 16; off > 0; off >>= 1)
        sum += __shfl_xor_sync(0xFFFFFFFFu, sum, off);

    const float inv = 1.0f / sum;
#pragma unroll
    for (int j = 0; j < 16; j++) v[j] *= inv;

    // PV: hid[w*32 + d] = sum_m v[m] * V[b*512+m][w*32+d]
    const int rg = l >> 3;
    const float* Vb = vmat + (long)b * 131072 + w * 32 + (l & 7) * 4;
    float4 acc = make_float4(0.f, 0.f, 0.f, 0.f);
#pragma unroll
    for (int j = 0; j < 8; j++) {
        float s0v = v[2 * j], s1v = v[2 * j + 1];
#pragma unroll
        for (int g = 0; g < 16; g++) {
            int r = j * 64 + g * 4 + rg;
            float4 vv = *(const float4*)(Vb + (long)r * 256);
            int src = g * 2 + (rg >> 1);
            float e0 = __shfl_sync(0xFFFFFFFFu, s0v, src);
            float e1 = __shfl_sync(0xFFFFFFFFu, s1v, src);
            float av = (rg & 1) ? e1 : e0;
            acc.x += av * vv.x;
            acc.y += av * vv.y;
            acc.z += av * vv.z;
            acc.w += av * vv.w;
        }
    }
#pragma unroll
    for (int off = 8; off <= 16; off <<= 1) {
        acc.x += __shfl_xor_sync(0xFFFFFFFFu, acc.x, off);
        acc.y += __shfl_xor_sync(0xFFFFFFFFu, acc.y, off);
        acc.z += __shfl_xor_sync(0xFFFFFFFFu, acc.z, off);
        acc.w += __shfl_xor_sync(0xFFFFFFFFu, acc.w, off);
    }
    if (l < 8)
        *(float4*)(hidS + w * 32 + l * 4) = acc;
    __syncthreads();

    // out-projection: out[bn][t] = bout[t] + sum_c hidS[c] * Wout[c][t]
    float o0 = bout[t], o1 = 0.f, o2 = 0.f, o3 = 0.f;
    const float* Wc = Wout + t;
#pragma unroll 4
    for (int c4 = 0; c4 < 64; c4++) {
        float4 hv = *(const float4*)(hidS + c4 * 4);
        o0 += hv.x * Wc[(c4 * 4 + 0) * 256];
        o1 += hv.y * Wc[(c4 * 4 + 1) * 256];
        o2 += hv.z * Wc[(c4 * 4 + 2) * 256];
        o3 += hv.w * Wc[(c4 * 4 + 3) * 256];
    }
    out[bn * 256 + t] = (o0 + o1) + (o2 + o3);
}

extern "C" void kernel_launch(void* const* d_in, const int* in_sizes, int n_in,
                              void* d_out, int out_size)
{
    const float* iq    = (const float*)d_in[0];
    const float* ik    = (const float*)d_in[1];
    const float* iv    = (const float*)d_in[2];
    const float* embed = (const float*)d_in[3];
    const float* Wq    = (const float*)d_in[4];
    const float* Wk    = (const float*)d_in[5];
    const float* Wv    = (const float*)d_in[6];
    const float* Wp    = (const float*)d_in[7];
    const float* Wout  = (const float*)d_in[8];
    const float* bout  = (const float*)d_in[9];
    float* out = (float*)d_out;

    float *q, *k, *v, *wq;
    cudaGetSymbolAddress((void**)&q,  g_q);
    cudaGetSymbolAddress((void**)&k,  g_k);
    cudaGetSymbolAddress((void**)&v,  g_v);
    cudaGetSymbolAddress((void**)&wq, g_wq);

    // 1. q/k/v projections (q scaled)
    k_gemm_qkv<<<dim3(16, 4, 3), 256>>>(iq, ik, iv, Wq, Wk, Wv, q, k, v);

    // 2. wq[h] = Q_h @ Wp_h^T
    k_gemm_wq<<<dim3(16, 4, 8), 256>>>(q, Wp, wq);

    // 3. fused scores_p + scores_e + softmax + attn@V + out-projection
    k_fused<<<dim3(512, 2), 256>>>(embed, wq, q, k, v, Wout, bout, out);
}

// round 10
// speedup vs baseline: 1.1940x; 1.1940x over previous
#include <cuda_runtime.h>

// RPE MHA, sm_100a. B=2, N=M=512, C=256, H=8, D=32.
// scores_p = embed . wq with wq = Wp-projected q (avoids projecting embed).
// R9 = R7 structure (known-good 202us) + out-projection fused into k_fused.
// The R8 q.kT-in-loop fusion is reverted (exposed L2 latency in hot loop).

#define SCALE_Q 0.17677669529663687f  // 32^-0.5, folded into q projection

__device__ float g_q[1024 * 256];
__device__ float g_k[1024 * 256];
__device__ float g_v[1024 * 256];
__device__ float g_wq[8 * 1024 * 256];     // [h][bn][c]
__device__ float g_se[16 * 512 * 512];     // [b*8+h][n][m]

// ---------------------------------------------------------------------------
// 64x64 tiled fp32 GEMM, 256 threads, K-tile 16, register double-buffered.
// BT=false: C = A[m][k] @ B[k][n].  BT=true: C = A[m][k] @ B[n][k].
// ---------------------------------------------------------------------------
template <bool BT>
__device__ __forceinline__ void gemm_body(
    const float* __restrict__ A, int lda,
    const float* __restrict__ B, int ldb,
    float* __restrict__ C, int ldc,
    int N, int K, float scale, const float* __restrict__ bias)
{
    __shared__ float As[64][20];
    __shared__ float Bs[16][68];

    const int tid = threadIdx.x;
    const int m0 = blockIdx.x * 64;
    const int n0 = blockIdx.y * 64;
    const int lr = tid >> 2;
    const int lc = (tid & 3) << 2;
    const int bk = tid >> 4;
    const int bn_ = (tid & 15) << 2;
    const int ty = tid >> 4;
    const int tx = tid & 15;

    float acc[4][4];
#pragma unroll
    for (int i = 0; i < 4; i++)
#pragma unroll
        for (int j = 0; j < 4; j++) acc[i][j] = 0.0f;

    float4 a4 = *(const float4*)(A + (long)(m0 + lr) * lda + lc);
    float4 b4;
    if (BT) {
        b4 = *(const float4*)(B + (long)(n0 + lr) * ldb + lc);
    } else {
        b4 = make_float4(0.f, 0.f, 0.f, 0.f);
        if (n0 + bn_ < N)
            b4 = *(const float4*)(B + (long)bk * ldb + n0 + bn_);
    }

    for (int k0 = 0; k0 < K; k0 += 16) {
        *(float4*)&As[lr][lc] = a4;
        if (BT) {
            Bs[lc + 0][lr] = b4.x;
            Bs[lc + 1][lr] = b4.y;
            Bs[lc + 2][lr] = b4.z;
            Bs[lc + 3][lr] = b4.w;
        } else {
            *(float4*)&Bs[bk][bn_] = b4;
        }
        __syncthreads();

        if (k0 + 16 < K) {
            a4 = *(const float4*)(A + (long)(m0 + lr) * lda + k0 + 16 + lc);
            if (BT) {
                b4 = *(const float4*)(B + (long)(n0 + lr) * ldb + k0 + 16 + lc);
            } else {
                b4 = make_float4(0.f, 0.f, 0.f, 0.f);
                if (n0 + bn_ < N)
                    b4 = *(const float4*)(B + (long)(k0 + 16 + bk) * ldb + n0 + bn_);
            }
        }

#pragma unroll
        for (int kk = 0; kk < 16; kk++) {
            float a[4];
#pragma unroll
            for (int i = 0; i < 4; i++) a[i] = As[ty * 4 + i][kk];
            float4 bb = *(const float4*)&Bs[kk][tx * 4];
#pragma unroll
            for (int i = 0; i < 4; i++) {
                acc[i][0] += a[i] * bb.x;
                acc[i][1] += a[i] * bb.y;
                acc[i][2] += a[i] * bb.z;
                acc[i][3] += a[i] * bb.w;
            }
        }
        __syncthreads();
    }

#pragma unroll
    for (int i = 0; i < 4; i++) {
#pragma unroll
        for (int j = 0; j < 4; j++) {
            int nn = n0 + tx * 4 + j;
            if (nn < N) {
                float val = acc[i][j] * scale;
                if (bias) val += bias[nn];
                C[(long)(m0 + ty * 4 + i) * ldc + nn] = val;
            }
        }
    }
}

// q/k/v projections batched over grid.z
__global__ void __launch_bounds__(256) k_gemm_qkv(
    const float* Aq, const float* Ak, const float* Av,
    const float* Bq, const float* Bk, const float* Bv,
    float* Cq, float* Ck, float* Cv)
{
    int z = blockIdx.z;
    const float* A = (z == 0) ? Aq : (z == 1) ? Ak : Av;
    const float* B = (z == 0) ? Bq : (z == 1) ? Bk : Bv;
    float*       C = (z == 0) ? Cq : (z == 1) ? Ck : Cv;
    gemm_body<false>(A, 256, B, 256, C, 256, 256, 256,
                     (z == 0) ? SCALE_Q : 1.0f, nullptr);
}

// Combined wq + scores_e (both depend only on q/k). grid (16, 8, 24).
//   z in [0,8):  wq[h] = Q_h @ Wp_h^T     (M=1024, N=256, K=32)
//   z in [8,24): se[b*8+h] = Q_h @ K_h^T  (M=512,  N=512, K=32)
__global__ void __launch_bounds__(256) k_wq_se(
    const float* __restrict__ q, const float* __restrict__ kmat,
    const float* __restrict__ Wp,
    float* __restrict__ wqo, float* __restrict__ seo)
{
    int z = blockIdx.z;
    if (z < 8) {
        if (blockIdx.y >= 4) return;
        gemm_body<true>(q + z * 32, 256,
                        Wp + z * 32, 256,
                        wqo + (long)z * 262144, 256,
                        256, 32, 1.0f, nullptr);
    } else {
        if (blockIdx.x >= 8) return;
        int zz = z - 8, bb = zz >> 3, hh = zz & 7;
        gemm_body<true>(q + (long)bb * 131072 + hh * 32, 256,
                        kmat + (long)bb * 131072 + hh * 32, 256,
                        seo + (long)zz * 262144, 512,
                        512, 32, 1.0f, nullptr);
    }
}

// ---------------------------------------------------------------------------
// Fused: scores_p + scores_e(add) + softmax + attn@V + out-projection.
// CTA per (b,n), 256 threads. Warp w owns rows m in [64w, 64w+64) for the
// score phase, head w for softmax + PV; whole CTA does the out-projection.
// ---------------------------------------------------------------------------
__device__ __forceinline__ float reduce8(const float* a, int l)
{
    float r[4];
#pragma unroll
    for (int j = 0; j < 4; j++) {
        float send = (l & 1) ? a[j] : a[j + 4];
        float keep = (l & 1) ? a[j + 4] : a[j];
        r[j] = keep + __shfl_xor_sync(0xFFFFFFFFu, send, 1);
    }
    float r2[2];
#pragma unroll
    for (int j = 0; j < 2; j++) {
        float send = (l & 2) ? r[j] : r[j + 2];
        float keep = (l & 2) ? r[j + 2] : r[j];
        r2[j] = keep + __shfl_xor_sync(0xFFFFFFFFu, send, 2);
    }
    float send = (l & 4) ? r2[0] : r2[1];
    float keep = (l & 4) ? r2[1] : r2[0];
    float s = keep + __shfl_xor_sync(0xFFFFFFFFu, send, 4);
    s += __shfl_xor_sync(0xFFFFFFFFu, s, 8);
    s += __shfl_xor_sync(0xFFFFFFFFu, s, 16);
    return s;
}

__global__ void __launch_bounds__(256, 2) k_fused(
    const float* __restrict__ embed,  // [b][n][m][c]
    const float* __restrict__ wq,     // [h][bn][c]
    const float* __restrict__ se,     // [b*8+h][n][m]
    const float* __restrict__ vmat,   // [b*512+m][c]
    const float* __restrict__ Wout,   // [c][c']
    const float* __restrict__ bout,   // [c']
    float* __restrict__ out)          // [bn][c']
{
    __shared__ float S[8 * 520];      // [h][m], pitch 520
    __shared__ float hidS[256];

    const int n = blockIdx.x;
    const int b = blockIdx.y;
    const int t = threadIdx.x;
    const int w = t >> 5, l = t & 31;
    const long bn = (long)b * 512 + n;

    // per-lane wq slice: channels 4l..4l+3 and 128+4l..128+4l+3, 8 heads
    float4 wq0[8], wq1[8];
#pragma unroll
    for (int h = 0; h < 8; h++) {
        const float* wp = wq + ((long)h * 1024 + bn) * 256;
        wq0[h] = *(const float4*)(wp + 4 * l);
        wq1[h] = *(const float4*)(wp + 128 + 4 * l);
    }
    const int hlane = ((l & 1) << 2) | (l & 2) | ((l & 4) >> 2);

    const float4* E = (const float4*)(embed + bn * 131072L) + (long)(w << 6) * 64;

    // prime prefetch: 2 embed rows
    float4 p0 = E[l], p1 = E[32 + l], p2 = E[64 + l], p3 = E[96 + l];

    for (int i = 0; i < 64; i += 2) {
        float4 x0 = p0, x1 = p1, y0 = p2, y1 = p3;
        if (i + 2 < 64) {
            const float4* En = E + (i + 2) * 64;
            p0 = En[l]; p1 = En[32 + l]; p2 = En[64 + l]; p3 = En[96 + l];
        }

        float a[8], c[8];
#pragma unroll
        for (int h = 0; h < 8; h++) {
            a[h] = x0.x * wq0[h].x + x0.y * wq0[h].y
                 + x0.z * wq0[h].z + x0.w * wq0[h].w
                 + x1.x * wq1[h].x + x1.y * wq1[h].y
                 + x1.z * wq1[h].z + x1.w * wq1[h].w;
            c[h] = y0.x * wq0[h].x + y0.y * wq0[h].y
                 + y0.z * wq0[h].z + y0.w * wq0[h].w
                 + y1.x * wq1[h].x + y1.y * wq1[h].y
                 + y1.z * wq1[h].z + y1.w * wq1[h].w;
        }
        float sA = reduce8(a, l);
        float sB = reduce8(c, l);
        if (l < 8) {
            S[hlane * 520 + (w << 6) + i]     = sA;
            S[hlane * 520 + (w << 6) + i + 1] = sB;
        }
    }
    __syncthreads();

    // softmax: warp w -> head w; lane owns m = {64j + 2l, +1}, j = 0..7
    const float* Sr  = S + w * 520;
    const float* ser = se + (long)(b * 8 + w) * 262144 + (long)n * 512;
    float v[16];
    float mx = -3.0e38f;
#pragma unroll
    for (int j = 0; j < 8; j++) {
        float2 sv = *(const float2*)(Sr  + j * 64 + l * 2);
        float2 ev = *(const float2*)(ser + j * 64 + l * 2);
        v[2 * j]     = sv.x + ev.x;
        v[2 * j + 1] = sv.y + ev.y;
        mx = fmaxf(mx, fmaxf(v[2 * j], v[2 * j + 1]));
    }
#pragma unroll
    for (int off = 16; off > 0; off >>= 1)
        mx = fmaxf(mx, __shfl_xor_sync(0xFFFFFFFFu, mx, off));

    float sum = 0.f;
#pragma unroll
    for (int j = 0; j < 16; j++) {
        v[j] = __expf(v[j] - mx);
        sum += v[j];
    }
#pragma unroll
    for (int off = 16; off > 0; off >>= 1)
        sum += __shfl_xor_sync(0xFFFFFFFFu, sum, off);

    const float inv = 1.0f / sum;
#pragma unroll
    for (int j = 0; j < 16; j++) v[j] *= inv;

    // PV: hid[w*32 + d] = sum_m v[m] * V[b*512+m][w*32+d]
    const int rg = l >> 3;
    const float* Vb = vmat + (long)b * 131072 + w * 32 + (l & 7) * 4;
    float4 acc = make_float4(0.f, 0.f, 0.f, 0.f);
#pragma unroll
    for (int j = 0; j < 8; j++) {
        float s0v = v[2 * j], s1v = v[2 * j + 1];
#pragma unroll
        for (int g = 0; g < 16; g++) {
            int r = j * 64 + g * 4 + rg;
            float4 vv = *(const float4*)(Vb + (long)r * 256);
            int src = g * 2 + (rg >> 1);
            float e0 = __shfl_sync(0xFFFFFFFFu, s0v, src);
            float e1 = __shfl_sync(0xFFFFFFFFu, s1v, src);
            float av = (rg & 1) ? e1 : e0;
            acc.x += av * vv.x;
            acc.y += av * vv.y;
            acc.z += av * vv.z;
            acc.w += av * vv.w;
        }
    }
#pragma unroll
    for (int off = 8; off <= 16; off <<= 1) {
        acc.x += __shfl_xor_sync(0xFFFFFFFFu, acc.x, off);
        acc.y += __shfl_xor_sync(0xFFFFFFFFu, acc.y, off);
        acc.z += __shfl_xor_sync(0xFFFFFFFFu, acc.z, off);
        acc.w += __shfl_xor_sync(0xFFFFFFFFu, acc.w, off);
    }
    if (l < 8)
        *(float4*)(hidS + w * 32 + l * 4) = acc;
    __syncthreads();

    // out-projection: out[bn][t] = bout[t] + sum_c hidS[c] * Wout[c][t]
    float o0 = bout[t], o1 = 0.f, o2 = 0.f, o3 = 0.f;
    const float* Wc = Wout + t;
#pragma unroll 4
    for (int c4 = 0; c4 < 64; c4++) {
        float4 hv = *(const float4*)(hidS + c4 * 4);
        o0 += hv.x * Wc[(c4 * 4 + 0) * 256];
        o1 += hv.y * Wc[(c4 * 4 + 1) * 256];
        o2 += hv.z * Wc[(c4 * 4 + 2) * 256];
        o3 += hv.w * Wc[(c4 * 4 + 3) * 256];
    }
    out[bn * 256 + t] = (o0 + o1) + (o2 + o3);
}

extern "C" void kernel_launch(void* const* d_in, const int* in_sizes, int n_in,
                              void* d_out, int out_size)
{
    const float* iq    = (const float*)d_in[0];
    const float* ik    = (const float*)d_in[1];
    const float* iv    = (const float*)d_in[2];
    const float* embed = (const float*)d_in[3];
    const float* Wq    = (const float*)d_in[4];
    const float* Wk    = (const float*)d_in[5];
    const float* Wv    = (const float*)d_in[6];
    const float* Wp    = (const float*)d_in[7];
    const float* Wout  = (const float*)d_in[8];
    const float* bout  = (const float*)d_in[9];
    float* out = (float*)d_out;

    float *q, *k, *v, *wq, *se;
    cudaGetSymbolAddress((void**)&q,  g_q);
    cudaGetSymbolAddress((void**)&k,  g_k);
    cudaGetSymbolAddress((void**)&v,  g_v);
    cudaGetSymbolAddress((void**)&wq, g_wq);
    cudaGetSymbolAddress((void**)&se, g_se);

    // 1. q/k/v projections (q scaled)
    k_gemm_qkv<<<dim3(16, 4, 3), 256>>>(iq, ik, iv, Wq, Wk, Wv, q, k, v);

    // 2. wq + scores_e (merged)
    k_wq_se<<<dim3(16, 8, 24), 256>>>(q, k, Wp, wq, se);

    // 3. fused scores_p + scores_e + softmax + attn@V + out-projection
    k_fused<<<dim3(512, 2), 256>>>(embed, wq, se, v, Wout, bout, out);
}

// round 13
// speedup vs baseline: 1.3370x; 1.1197x over previous
#include <cuda_runtime.h>

// RPE MHA, sm_100a. B=2, N=M=512, C=256, H=8, D=32.
// scores_p = embed . wq with wq = Wp-projected q (avoids projecting embed).
// R12 = R10/R11 resubmitted verbatim (both benches were infra failures):
//   fused: two-buffer 4-row phase pipeline -> 8 LDGs in flight per warp
//   sides: 32x64 tiles, K-tile 32 (2x CTAs, half the syncs, more MLP)

#define SCALE_Q 0.17677669529663687f  // 32^-0.5, folded into q projection

__device__ float g_q[1024 * 256];
__device__ float g_k[1024 * 256];
__device__ float g_v[1024 * 256];
__device__ float g_wq[8 * 1024 * 256];     // [h][bn][c]
__device__ float g_se[16 * 512 * 512];     // [b*8+h][n][m]
__device__ float g_hid[1024 * 256];        // [bn][c]

// ---------------------------------------------------------------------------
// 32x64 tiled fp32 GEMM, 256 threads, K-tile 32, register double-buffered.
// BT=false: C = A[m][k] @ B[k][n].  BT=true: C = A[m][k] @ B[n][k].
// M multiple of 32, K multiple of 32, N guarded.
// ---------------------------------------------------------------------------
template <bool BT>
__device__ __forceinline__ void gemm_body(
    const float* __restrict__ A, int lda,
    const float* __restrict__ B, int ldb,
    float* __restrict__ C, int ldc,
    int N, int K, float scale, const float* __restrict__ bias)
{
    __shared__ float As[32][36];
    __shared__ float Bs[32][68];

    const int tid = threadIdx.x;
    const int m0 = blockIdx.x * 32;
    const int n0 = blockIdx.y * 64;

    const int lr = tid >> 3;            // 0..31  A row
    const int lc = (tid & 7) << 2;      // 0..28  A k-col (float4)
    const int bk = tid >> 4;            // 0..15  B k-row (NN)
    const int bn_ = (tid & 15) << 2;    // 0..60  B n-col (NN)
    const int nr0 = tid >> 3;           // 0..31  B n-row chunk 0 (NT)
    const int nr1 = (tid + 256) >> 3;   // 32..63 B n-row chunk 1 (NT)
    const int nc = (tid & 7) << 2;      // 0..28  B k-col (NT)
    const int ty = tid >> 4;            // 0..15 -> rows 2ty, 2ty+1
    const int tx = tid & 15;            // cols 4tx..4tx+3

    float acc[2][4];
#pragma unroll
    for (int i = 0; i < 2; i++)
#pragma unroll
        for (int j = 0; j < 4; j++) acc[i][j] = 0.0f;

    // prime first K-tile
    float4 a4 = *(const float4*)(A + (long)(m0 + lr) * lda + lc);
    float4 t0, t1;
    if (BT) {
        t0 = *(const float4*)(B + (long)(n0 + nr0) * ldb + nc);
        t1 = *(const float4*)(B + (long)(n0 + nr1) * ldb + nc);
    } else {
        t0 = make_float4(0.f, 0.f, 0.f, 0.f);
        t1 = make_float4(0.f, 0.f, 0.f, 0.f);
        if (n0 + bn_ < N) {
            t0 = *(const float4*)(B + (long)bk * ldb + n0 + bn_);
            t1 = *(const float4*)(B + (long)(bk + 16) * ldb + n0 + bn_);
        }
    }

    for (int k0 = 0; k0 < K; k0 += 32) {
        *(float4*)&As[lr][lc] = a4;
        if (BT) {
            Bs[nc + 0][nr0] = t0.x;
            Bs[nc + 1][nr0] = t0.y;
            Bs[nc + 2][nr0] = t0.z;
            Bs[nc + 3][nr0] = t0.w;
            Bs[nc + 0][nr1] = t1.x;
            Bs[nc + 1][nr1] = t1.y;
            Bs[nc + 2][nr1] = t1.z;
            Bs[nc + 3][nr1] = t1.w;
        } else {
            *(float4*)&Bs[bk][bn_]      = t0;
            *(float4*)&Bs[bk + 16][bn_] = t1;
        }
        __syncthreads();

        if (k0 + 32 < K) {
            a4 = *(const float4*)(A + (long)(m0 + lr) * lda + k0 + 32 + lc);
            if (BT) {
                t0 = *(const float4*)(B + (long)(n0 + nr0) * ldb + k0 + 32 + nc);
                t1 = *(const float4*)(B + (long)(n0 + nr1) * ldb + k0 + 32 + nc);
            } else {
                t0 = make_float4(0.f, 0.f, 0.f, 0.f);
                t1 = make_float4(0.f, 0.f, 0.f, 0.f);
                if (n0 + bn_ < N) {
                    t0 = *(const float4*)(B + (long)(k0 + 32 + bk) * ldb + n0 + bn_);
                    t1 = *(const float4*)(B + (long)(k0 + 48 + bk) * ldb + n0 + bn_);
                }
            }
        }

#pragma unroll
        for (int kk = 0; kk < 32; kk++) {
            float a0 = As[ty * 2][kk];
            float a1 = As[ty * 2 + 1][kk];
            float4 bb = *(const float4*)&Bs[kk][tx * 4];
            acc[0][0] += a0 * bb.x;  acc[0][1] += a0 * bb.y;
            acc[0][2] += a0 * bb.z;  acc[0][3] += a0 * bb.w;
            acc[1][0] += a1 * bb.x;  acc[1][1] += a1 * bb.y;
            acc[1][2] += a1 * bb.z;  acc[1][3] += a1 * bb.w;
        }
        __syncthreads();
    }

#pragma unroll
    for (int i = 0; i < 2; i++) {
#pragma unroll
        for (int j = 0; j < 4; j++) {
            int nn = n0 + tx * 4 + j;
            if (nn < N) {
                float val = acc[i][j] * scale;
                if (bias) val += bias[nn];
                C[(long)(m0 + ty * 2 + i) * ldc + nn] = val;
            }
        }
    }
}

// q/k/v projections batched over grid.z
__global__ void __launch_bounds__(256) k_gemm_qkv(
    const float* Aq, const float* Ak, const float* Av,
    const float* Bq, const float* Bk, const float* Bv,
    float* Cq, float* Ck, float* Cv)
{
    int z = blockIdx.z;
    const float* A = (z == 0) ? Aq : (z == 1) ? Ak : Av;
    const float* B = (z == 0) ? Bq : (z == 1) ? Bk : Bv;
    float*       C = (z == 0) ? Cq : (z == 1) ? Ck : Cv;
    gemm_body<false>(A, 256, B, 256, C, 256, 256, 256,
                     (z == 0) ? SCALE_Q : 1.0f, nullptr);
}

// Combined wq + scores_e (K=32 -> single K-tile, no loop). grid (32, 8, 24).
//   z in [0,8):  wq[h] = Q_h @ Wp_h^T     (M=1024, N=256)  [by < 4]
//   z in [8,24): se[b*8+h] = Q_h @ K_h^T  (M=512,  N=512)  [bx < 16]
__global__ void __launch_bounds__(256) k_wq_se(
    const float* __restrict__ q, const float* __restrict__ kmat,
    const float* __restrict__ Wp,
    float* __restrict__ wqo, float* __restrict__ seo)
{
    int z = blockIdx.z;
    if (z < 8) {
        if (blockIdx.y >= 4) return;
        gemm_body<true>(q + z * 32, 256,
                        Wp + z * 32, 256,
                        wqo + (long)z * 262144, 256,
                        256, 32, 1.0f, nullptr);
    } else {
        if (blockIdx.x >= 16) return;
        int zz = z - 8, bb = zz >> 3, hh = zz & 7;
        gemm_body<true>(q + (long)bb * 131072 + hh * 32, 256,
                        kmat + (long)bb * 131072 + hh * 32, 256,
                        seo + (long)zz * 262144, 512,
                        512, 32, 1.0f, nullptr);
    }
}

// out = hidden @ Wout + bout
__global__ void __launch_bounds__(256) k_gemm_out(
    const float* A, const float* B, float* C, const float* bias)
{
    gemm_body<false>(A, 256, B, 256, C, 256, 256, 256, 1.0f, bias);
}

// ---------------------------------------------------------------------------
// Fused scores_p + scores_e(add) + softmax + attn@V -> hidden.
// CTA per (b,n), 256 threads. Warp w owns rows m in [64w, 64w+64) for the
// score phase, head w for softmax + PV.
// Two 4-float4 buffers; each half-phase consumes one buffer then reloads it
// for 2 phases later -> 8 LDG.128 in flight per warp at steady state.
// ---------------------------------------------------------------------------
__device__ __forceinline__ float reduce8(const float* a, int l)
{
    float r[4];
#pragma unroll
    for (int j = 0; j < 4; j++) {
        float send = (l & 1) ? a[j] : a[j + 4];
        float keep = (l & 1) ? a[j + 4] : a[j];
        r[j] = keep + __shfl_xor_sync(0xFFFFFFFFu, send, 1);
    }
    float r2[2];
#pragma unroll
    for (int j = 0; j < 2; j++) {
        float send = (l & 2) ? r[j] : r[j + 2];
        float keep = (l & 2) ? r[j + 2] : r[j];
        r2[j] = keep + __shfl_xor_sync(0xFFFFFFFFu, send, 2);
    }
    float send = (l & 4) ? r2[0] : r2[1];
    float keep = (l & 4) ? r2[1] : r2[0];
    float s = keep + __shfl_xor_sync(0xFFFFFFFFu, send, 4);
    s += __shfl_xor_sync(0xFFFFFFFFu, s, 8);
    s += __shfl_xor_sync(0xFFFFFFFFu, s, 16);
    return s;
}

// compute scores for 2 rows held in (x0,x1 / y0,y1) and store to S
__device__ __forceinline__ void score2(
    float4 x0, float4 x1, float4 y0, float4 y1,
    const float4* wq0, const float4* wq1,
    float* S, int mbase, int hlane, int l)
{
    float a[8], c[8];
#pragma unroll
    for (int h = 0; h < 8; h++) {
        a[h] = x0.x * wq0[h].x + x0.y * wq0[h].y
             + x0.z * wq0[h].z + x0.w * wq0[h].w
             + x1.x * wq1[h].x + x1.y * wq1[h].y
             + x1.z * wq1[h].z + x1.w * wq1[h].w;
        c[h] = y0.x * wq0[h].x + y0.y * wq0[h].y
             + y0.z * wq0[h].z + y0.w * wq0[h].w
             + y1.x * wq1[h].x + y1.y * wq1[h].y
             + y1.z * wq1[h].z + y1.w * wq1[h].w;
    }
    float sA = reduce8(a, l);
    float sB = reduce8(c, l);
    if (l < 8) {
        S[hlane * 520 + mbase]     = sA;
        S[hlane * 520 + mbase + 1] = sB;
    }
}

__global__ void __launch_bounds__(256, 2) k_fused(
    const float* __restrict__ embed,  // [b][n][m][c]
    const float* __restrict__ wq,     // [h][bn][c]
    const float* __restrict__ se,     // [b*8+h][n][m]
    const float* __restrict__ vmat,   // [b*512+m][c]
    float* __restrict__ hid)          // [bn][c]
{
    __shared__ float S[8 * 520];      // [h][m], pitch 520

    const int n = blockIdx.x;
    const int b = blockIdx.y;
    const int t = threadIdx.x;
    const int w = t >> 5, l = t & 31;
    const long bn = (long)b * 512 + n;

    // per-lane wq slice: channels 4l..4l+3 and 128+4l..128+4l+3, 8 heads
    float4 wq0[8], wq1[8];
#pragma unroll
    for (int h = 0; h < 8; h++) {
        const float* wp = wq + ((long)h * 1024 + bn) * 256;
        wq0[h] = *(const float4*)(wp + 4 * l);
        wq1[h] = *(const float4*)(wp + 128 + 4 * l);
    }
    const int hlane = ((l & 1) << 2) | (l & 2) | ((l & 4) >> 2);

    const float4* E = (const float4*)(embed + bn * 131072L) + (long)(w << 6) * 64;

    // prime both buffers: rows 0,1 (A) and rows 2,3 (B)
    float4 A0 = E[l],       A1 = E[32 + l],  A2 = E[64 + l],  A3 = E[96 + l];
    float4 B0 = E[128 + l], B1 = E[160 + l], B2 = E[192 + l], B3 = E[224 + l];

    for (int i = 0; i < 64; i += 4) {
        // phase 1: rows i, i+1 from buffer A, then reload A for rows i+4, i+5
        score2(A0, A1, A2, A3, wq0, wq1, S, (w << 6) + i, hlane, l);
        if (i + 4 < 64) {
            const float4* En = E + (i + 4) * 64;
            A0 = En[l]; A1 = En[32 + l]; A2 = En[64 + l]; A3 = En[96 + l];
        }
        // phase 2: rows i+2, i+3 from buffer B, then reload B for i+6, i+7
        score2(B0, B1, B2, B3, wq0, wq1, S, (w << 6) + i + 2, hlane, l);
        if (i + 4 < 64) {
            const float4* En = E + (i + 6) * 64;
            B0 = En[l]; B1 = En[32 + l]; B2 = En[64 + l]; B3 = En[96 + l];
        }
    }
    __syncthreads();

    // softmax: warp w -> head w; lane owns m = {64j + 2l, +1}, j = 0..7
    const float* Sr  = S + w * 520;
    const float* ser = se + (long)(b * 8 + w) * 262144 + (long)n * 512;
    float v[16];
    float mx = -3.0e38f;
#pragma unroll
    for (int j = 0; j < 8; j++) {
        float2 sv = *(const float2*)(Sr  + j * 64 + l * 2);
        float2 ev = *(const float2*)(ser + j * 64 + l * 2);
        v[2 * j]     = sv.x + ev.x;
        v[2 * j + 1] = sv.y + ev.y;
        mx = fmaxf(mx, fmaxf(v[2 * j], v[2 * j + 1]));
    }
#pragma unroll
    for (int off = 16; off > 0; off >>= 1)
        mx = fmaxf(mx, __shfl_xor_sync(0xFFFFFFFFu, mx, off));

    float sum = 0.f;
#pragma unroll
    for (int j = 0; j < 16; j++) {
        v[j] = __expf(v[j] - mx);
        sum += v[j];
    }
#pragma unroll
    for (int off = 16; off > 0; off >>= 1)
        sum += __shfl_xor_sync(0xFFFFFFFFu, sum, off);

    const float inv = 1.0f / sum;
#pragma unroll
    for (int j = 0; j < 16; j++) v[j] *= inv;

    // PV: hid[w*32 + d] = sum_m v[m] * V[b*512+m][w*32+d]
    const int rg = l >> 3;
    const float* Vb = vmat + (long)b * 131072 + w * 32 + (l & 7) * 4;
    float4 acc = make_float4(0.f, 0.f, 0.f, 0.f);
#pragma unroll
    for (int j = 0; j < 8; j++) {
        float s0v = v[2 * j], s1v = v[2 * j + 1];
#pragma unroll
        for (int g = 0; g < 16; g++) {
            int r = j * 64 + g * 4 + rg;
            float4 vv = *(const float4*)(Vb + (long)r * 256);
            int src = g * 2 + (rg >> 1);
            float e0 = __shfl_sync(0xFFFFFFFFu, s0v, src);
            float e1 = __shfl_sync(0xFFFFFFFFu, s1v, src);
            float av = (rg & 1) ? e1 : e0;
            acc.x += av * vv.x;
            acc.y += av * vv.y;
            acc.z += av * vv.z;
            acc.w += av * vv.w;
        }
    }
#pragma unroll
    for (int off = 8; off <= 16; off <<= 1) {
        acc.x += __shfl_xor_sync(0xFFFFFFFFu, acc.x, off);
        acc.y += __shfl_xor_sync(0xFFFFFFFFu, acc.y, off);
        acc.z += __shfl_xor_sync(0xFFFFFFFFu, acc.z, off);
        acc.w += __shfl_xor_sync(0xFFFFFFFFu, acc.w, off);
    }
    if (l < 8)
        *(float4*)(hid + bn * 256 + w * 32 + l * 4) = acc;
}

extern "C" void kernel_launch(void* const* d_in, const int* in_sizes, int n_in,
                              void* d_out, int out_size)
{
    const float* iq    = (const float*)d_in[0];
    const float* ik    = (const float*)d_in[1];
    const float* iv    = (const float*)d_in[2];
    const float* embed = (const float*)d_in[3];
    const float* Wq    = (const float*)d_in[4];
    const float* Wk    = (const float*)d_in[5];
    const float* Wv    = (const float*)d_in[6];
    const float* Wp    = (const float*)d_in[7];
    const float* Wout  = (const float*)d_in[8];
    const float* bout  = (const float*)d_in[9];
    float* out = (float*)d_out;

    float *q, *k, *v, *wq, *se, *hid;
    cudaGetSymbolAddress((void**)&q,   g_q);
    cudaGetSymbolAddress((void**)&k,   g_k);
    cudaGetSymbolAddress((void**)&v,   g_v);
    cudaGetSymbolAddress((void**)&wq,  g_wq);
    cudaGetSymbolAddress((void**)&se,  g_se);
    cudaGetSymbolAddress((void**)&hid, g_hid);

    // 1. q/k/v projections (q scaled)
    k_gemm_qkv<<<dim3(32, 4, 3), 256>>>(iq, ik, iv, Wq, Wk, Wv, q, k, v);

    // 2. wq + scores_e (merged, single K-tile)
    k_wq_se<<<dim3(32, 8, 24), 256>>>(q, k, Wp, wq, se);

    // 3. fused scores_p + scores_e + softmax + attn@V -> hidden
    k_fused<<<dim3(512, 2), 256>>>(embed, wq, se, v, hid);

    // 4. out = hidden @ Wout + bout
    k_gemm_out<<<dim3(32, 4, 1), 256>>>(hid, Wout, out, bout);
}

// round 14
// speedup vs baseline: 1.3791x; 1.0315x over previous
#include <cuda_runtime.h>

// RPE MHA, sm_100a. B=2, N=M=512, C=256, H=8, D=32.
// scores_p = embed . wq with wq = Wp-projected q (avoids projecting embed).
// R13: fused score loop staged through cp.async (4-stage x 2-row smem ring,
// 16 x 512B in flight per warp, no register WAR) -> DRAM-bound for real.
// Sides unchanged from R12 (32x64 tiles, K-tile 32).

#define SCALE_Q 0.17677669529663687f  // 32^-0.5, folded into q projection

__device__ float g_q[1024 * 256];
__device__ float g_k[1024 * 256];
__device__ float g_v[1024 * 256];
__device__ float g_wq[8 * 1024 * 256];     // [h][bn][c]
__device__ float g_se[16 * 512 * 512];     // [b*8+h][n][m]
__device__ float g_hid[1024 * 256];        // [bn][c]

// fused kernel dynamic smem: ES ring 16384 floats + S 8*520 floats
#define FK_SMEM_BYTES ((16384 + 8 * 520) * 4)

// ---------------------------------------------------------------------------
// cp.async helpers
// ---------------------------------------------------------------------------
__device__ __forceinline__ void cp16(float* dst_smem, const float* src)
{
    unsigned d = (unsigned)__cvta_generic_to_shared(dst_smem);
    asm volatile("cp.async.cg.shared.global [%0], [%1], 16;" :: "r"(d), "l"(src));
}
__device__ __forceinline__ void cp_commit()
{
    asm volatile("cp.async.commit_group;");
}
__device__ __forceinline__ void cp_wait3()
{
    asm volatile("cp.async.wait_group 3;");
}

// ---------------------------------------------------------------------------
// 32x64 tiled fp32 GEMM, 256 threads, K-tile 32, register double-buffered.
// BT=false: C = A[m][k] @ B[k][n].  BT=true: C = A[m][k] @ B[n][k].
// ---------------------------------------------------------------------------
template <bool BT>
__device__ __forceinline__ void gemm_body(
    const float* __restrict__ A, int lda,
    const float* __restrict__ B, int ldb,
    float* __restrict__ C, int ldc,
    int N, int K, float scale, const float* __restrict__ bias)
{
    __shared__ float As[32][36];
    __shared__ float Bs[32][68];

    const int tid = threadIdx.x;
    const int m0 = blockIdx.x * 32;
    const int n0 = blockIdx.y * 64;

    const int lr = tid >> 3;
    const int lc = (tid & 7) << 2;
    const int bk = tid >> 4;
    const int bn_ = (tid & 15) << 2;
    const int nr0 = tid >> 3;
    const int nr1 = (tid + 256) >> 3;
    const int nc = (tid & 7) << 2;
    const int ty = tid >> 4;
    const int tx = tid & 15;

    float acc[2][4];
#pragma unroll
    for (int i = 0; i < 2; i++)
#pragma unroll
        for (int j = 0; j < 4; j++) acc[i][j] = 0.0f;

    float4 a4 = *(const float4*)(A + (long)(m0 + lr) * lda + lc);
    float4 t0, t1;
    if (BT) {
        t0 = *(const float4*)(B + (long)(n0 + nr0) * ldb + nc);
        t1 = *(const float4*)(B + (long)(n0 + nr1) * ldb + nc);
    } else {
        t0 = make_float4(0.f, 0.f, 0.f, 0.f);
        t1 = make_float4(0.f, 0.f, 0.f, 0.f);
        if (n0 + bn_ < N) {
            t0 = *(const float4*)(B + (long)bk * ldb + n0 + bn_);
            t1 = *(const float4*)(B + (long)(bk + 16) * ldb + n0 + bn_);
        }
    }

    for (int k0 = 0; k0 < K; k0 += 32) {
        *(float4*)&As[lr][lc] = a4;
        if (BT) {
            Bs[nc + 0][nr0] = t0.x;
            Bs[nc + 1][nr0] = t0.y;
            Bs[nc + 2][nr0] = t0.z;
            Bs[nc + 3][nr0] = t0.w;
            Bs[nc + 0][nr1] = t1.x;
            Bs[nc + 1][nr1] = t1.y;
            Bs[nc + 2][nr1] = t1.z;
            Bs[nc + 3][nr1] = t1.w;
        } else {
            *(float4*)&Bs[bk][bn_]      = t0;
            *(float4*)&Bs[bk + 16][bn_] = t1;
        }
        __syncthreads();

        if (k0 + 32 < K) {
            a4 = *(const float4*)(A + (long)(m0 + lr) * lda + k0 + 32 + lc);
            if (BT) {
                t0 = *(const float4*)(B + (long)(n0 + nr0) * ldb + k0 + 32 + nc);
                t1 = *(const float4*)(B + (long)(n0 + nr1) * ldb + k0 + 32 + nc);
            } else {
                t0 = make_float4(0.f, 0.f, 0.f, 0.f);
                t1 = make_float4(0.f, 0.f, 0.f, 0.f);
                if (n0 + bn_ < N) {
                    t0 = *(const float4*)(B + (long)(k0 + 32 + bk) * ldb + n0 + bn_);
                    t1 = *(const float4*)(B + (long)(k0 + 48 + bk) * ldb + n0 + bn_);
                }
            }
        }

#pragma unroll
        for (int kk = 0; kk < 32; kk++) {
            float a0 = As[ty * 2][kk];
            float a1 = As[ty * 2 + 1][kk];
            float4 bb = *(const float4*)&Bs[kk][tx * 4];
            acc[0][0] += a0 * bb.x;  acc[0][1] += a0 * bb.y;
            acc[0][2] += a0 * bb.z;  acc[0][3] += a0 * bb.w;
            acc[1][0] += a1 * bb.x;  acc[1][1] += a1 * bb.y;
            acc[1][2] += a1 * bb.z;  acc[1][3] += a1 * bb.w;
        }
        __syncthreads();
    }

#pragma unroll
    for (int i = 0; i < 2; i++) {
#pragma unroll
        for (int j = 0; j < 4; j++) {
            int nn = n0 + tx * 4 + j;
            if (nn < N) {
                float val = acc[i][j] * scale;
                if (bias) val += bias[nn];
                C[(long)(m0 + ty * 2 + i) * ldc + nn] = val;
            }
        }
    }
}

// q/k/v projections batched over grid.z
__global__ void __launch_bounds__(256) k_gemm_qkv(
    const float* Aq, const float* Ak, const float* Av,
    const float* Bq, const float* Bk, const float* Bv,
    float* Cq, float* Ck, float* Cv)
{
    int z = blockIdx.z;
    const float* A = (z == 0) ? Aq : (z == 1) ? Ak : Av;
    const float* B = (z == 0) ? Bq : (z == 1) ? Bk : Bv;
    float*       C = (z == 0) ? Cq : (z == 1) ? Ck : Cv;
    gemm_body<false>(A, 256, B, 256, C, 256, 256, 256,
                     (z == 0) ? SCALE_Q : 1.0f, nullptr);
}

// Combined wq + scores_e (K=32 -> single K-tile, no loop). grid (32, 8, 24).
__global__ void __launch_bounds__(256) k_wq_se(
    const float* __restrict__ q, const float* __restrict__ kmat,
    const float* __restrict__ Wp,
    float* __restrict__ wqo, float* __restrict__ seo)
{
    int z = blockIdx.z;
    if (z < 8) {
        if (blockIdx.y >= 4) return;
        gemm_body<true>(q + z * 32, 256,
                        Wp + z * 32, 256,
                        wqo + (long)z * 262144, 256,
                        256, 32, 1.0f, nullptr);
    } else {
        if (blockIdx.x >= 16) return;
        int zz = z - 8, bb = zz >> 3, hh = zz & 7;
        gemm_body<true>(q + (long)bb * 131072 + hh * 32, 256,
                        kmat + (long)bb * 131072 + hh * 32, 256,
                        seo + (long)zz * 262144, 512,
                        512, 32, 1.0f, nullptr);
    }
}

// out = hidden @ Wout + bout
__global__ void __launch_bounds__(256) k_gemm_out(
    const float* A, const float* B, float* C, const float* bias)
{
    gemm_body<false>(A, 256, B, 256, C, 256, 256, 256, 1.0f, bias);
}

// ---------------------------------------------------------------------------
// Fused scores_p + scores_e(add) + softmax + attn@V -> hidden.
// CTA per (b,n), 256 threads. Warp w owns rows m in [64w, 64w+64) for the
// score phase, head w for softmax + PV.
// Embed is staged through a per-warp 4-stage x 2-row cp.async ring in smem:
// 16 x 512B in flight per warp, loads fully decoupled from compute.
// Each lane reads back exactly the 16B words it copied, so wait_group alone
// provides visibility (no __syncwarp needed).
// ---------------------------------------------------------------------------
__device__ __forceinline__ float reduce8(const float* a, int l)
{
    float r[4];
#pragma unroll
    for (int j = 0; j < 4; j++) {
        float send = (l & 1) ? a[j] : a[j + 4];
        float keep = (l & 1) ? a[j + 4] : a[j];
        r[j] = keep + __shfl_xor_sync(0xFFFFFFFFu, send, 1);
    }
    float r2[2];
#pragma unroll
    for (int j = 0; j < 2; j++) {
        float send = (l & 2) ? r[j] : r[j + 2];
        float keep = (l & 2) ? r[j + 2] : r[j];
        r2[j] = keep + __shfl_xor_sync(0xFFFFFFFFu, send, 2);
    }
    float send = (l & 4) ? r2[0] : r2[1];
    float keep = (l & 4) ? r2[1] : r2[0];
    float s = keep + __shfl_xor_sync(0xFFFFFFFFu, send, 4);
    s += __shfl_xor_sync(0xFFFFFFFFu, s, 8);
    s += __shfl_xor_sync(0xFFFFFFFFu, s, 16);
    return s;
}

// compute scores for 2 rows held in (x0,x1 / y0,y1) and store to S
__device__ __forceinline__ void score2(
    float4 x0, float4 x1, float4 y0, float4 y1,
    const float4* wq0, const float4* wq1,
    float* S, int mbase, int hlane, int l)
{
    float a[8], c[8];
#pragma unroll
    for (int h = 0; h < 8; h++) {
        a[h] = x0.x * wq0[h].x + x0.y * wq0[h].y
             + x0.z * wq0[h].z + x0.w * wq0[h].w
             + x1.x * wq1[h].x + x1.y * wq1[h].y
             + x1.z * wq1[h].z + x1.w * wq1[h].w;
        c[h] = y0.x * wq0[h].x + y0.y * wq0[h].y
             + y0.z * wq0[h].z + y0.w * wq0[h].w
             + y1.x * wq1[h].x + y1.y * wq1[h].y
             + y1.z * wq1[h].z + y1.w * wq1[h].w;
    }
    float sA = reduce8(a, l);
    float sB = reduce8(c, l);
    if (l < 8) {
        S[hlane * 520 + mbase]     = sA;
        S[hlane * 520 + mbase + 1] = sB;
    }
}

__global__ void __launch_bounds__(256, 2) k_fused(
    const float* __restrict__ embed,  // [b][n][m][c]
    const float* __restrict__ wq,     // [h][bn][c]
    const float* __restrict__ se,     // [b*8+h][n][m]
    const float* __restrict__ vmat,   // [b*512+m][c]
    float* __restrict__ hid)          // [bn][c]
{
    extern __shared__ float sm[];
    // ES ring: [8 warps][4 stages][2 rows][256 floats] = 16384 floats (64KB)
    // S: [8 heads][520] after the ring
    float* S = sm + 16384;

    const int n = blockIdx.x;
    const int b = blockIdx.y;
    const int t = threadIdx.x;
    const int w = t >> 5, l = t & 31;
    const long bn = (long)b * 512 + n;

    // per-lane wq slice: channels 4l..4l+3 and 128+4l..128+4l+3, 8 heads
    float4 wq0[8], wq1[8];
#pragma unroll
    for (int h = 0; h < 8; h++) {
        const float* wp = wq + ((long)h * 1024 + bn) * 256;
        wq0[h] = *(const float4*)(wp + 4 * l);
        wq1[h] = *(const float4*)(wp + 128 + 4 * l);
    }
    const int hlane = ((l & 1) << 2) | (l & 2) | ((l & 4) >> 2);

    // warp's 64 embed rows; lane offset folded in
    const float* Eg = embed + bn * 131072L + (long)(w << 6) * 256 + l * 4;
    float* ESw = sm + (w << 11) + l * 4;    // warp ring base + lane offset

    // prime 4 stages (phases 0..3; stage s = rows 2s, 2s+1 = 512 floats)
#pragma unroll
    for (int s = 0; s < 4; s++) {
        const float* src = Eg + s * 512;
        float* d = ESw + s * 512;
        cp16(d,       src);
        cp16(d + 128, src + 128);
        cp16(d + 256, src + 256);
        cp16(d + 384, src + 384);
        cp_commit();
    }

#pragma unroll 4
    for (int i = 0; i < 32; i++) {
        const int slot = i & 3;
        cp_wait3();                       // stage i complete
        const float* Ap = ESw + slot * 512;
        float4 x0 = *(const float4*)(Ap);
        float4 x1 = *(const float4*)(Ap + 128);
        float4 y0 = *(const float4*)(Ap + 256);
        float4 y1 = *(const float4*)(Ap + 384);
        if (i + 4 < 32) {                 // refill slot for phase i+4
            const float* src = Eg + (i + 4) * 512;
            float* d = ESw + slot * 512;
            cp16(d,       src);
            cp16(d + 128, src + 128);
            cp16(d + 256, src + 256);
            cp16(d + 384, src + 384);
        }
        cp_commit();                      // always commit (keeps group count aligned)
        score2(x0, x1, y0, y1, wq0, wq1, S, (w << 6) + 2 * i, hlane, l);
    }
    __syncthreads();

    // softmax: warp w -> head w; lane owns m = {64j + 2l, +1}, j = 0..7
    const float* Sr  = S + w * 520;
    const float* ser = se + (long)(b * 8 + w) * 262144 + (long)n * 512;
    float v[16];
    float mx = -3.0e38f;
#pragma unroll
    for (int j = 0; j < 8; j++) {
        float2 sv = *(const float2*)(Sr  + j * 64 + l * 2);
        float2 ev = *(const float2*)(ser + j * 64 + l * 2);
        v[2 * j]     = sv.x + ev.x;
        v[2 * j + 1] = sv.y + ev.y;
        mx = fmaxf(mx, fmaxf(v[2 * j], v[2 * j + 1]));
    }
#pragma unroll
    for (int off = 16; off > 0; off >>= 1)
        mx = fmaxf(mx, __shfl_xor_sync(0xFFFFFFFFu, mx, off));

    float sum = 0.f;
#pragma unroll
    for (int j = 0; j < 16; j++) {
        v[j] = __expf(v[j] - mx);
        sum += v[j];
    }
#pragma unroll
    for (int off = 16; off > 0; off >>= 1)
        sum += __shfl_xor_sync(0xFFFFFFFFu, sum, off);

    const float inv = 1.0f / sum;
#pragma unroll
    for (int j = 0; j < 16; j++) v[j] *= inv;

    // PV: hid[w*32 + d] = sum_m v[m] * V[b*512+m][w*32+d]
    const int rg = l >> 3;
    const float* Vb = vmat + (long)b * 131072 + w * 32 + (l & 7) * 4;
    float4 acc = make_float4(0.f, 0.f, 0.f, 0.f);
#pragma unroll
    for (int j = 0; j < 8; j++) {
        float s0v = v[2 * j], s1v = v[2 * j + 1];
#pragma unroll
        for (int g = 0; g < 16; g++) {
            int r = j * 64 + g * 4 + rg;
            float4 vv = *(const float4*)(Vb + (long)r * 256);
            int src = g * 2 + (rg >> 1);
            float e0 = __shfl_sync(0xFFFFFFFFu, s0v, src);
            float e1 = __shfl_sync(0xFFFFFFFFu, s1v, src);
            float av = (rg & 1) ? e1 : e0;
            acc.x += av * vv.x;
            acc.y += av * vv.y;
            acc.z += av * vv.z;
            acc.w += av * vv.w;
        }
    }
#pragma unroll
    for (int off = 8; off <= 16; off <<= 1) {
        acc.x += __shfl_xor_sync(0xFFFFFFFFu, acc.x, off);
        acc.y += __shfl_xor_sync(0xFFFFFFFFu, acc.y, off);
        acc.z += __shfl_xor_sync(0xFFFFFFFFu, acc.z, off);
        acc.w += __shfl_xor_sync(0xFFFFFFFFu, acc.w, off);
    }
    if (l < 8)
        *(float4*)(hid + bn * 256 + w * 32 + l * 4) = acc;
}

extern "C" void kernel_launch(void* const* d_in, const int* in_sizes, int n_in,
                              void* d_out, int out_size)
{
    const float* iq    = (const float*)d_in[0];
    const float* ik    = (const float*)d_in[1];
    const float* iv    = (const float*)d_in[2];
    const float* embed = (const float*)d_in[3];
    const float* Wq    = (const float*)d_in[4];
    const float* Wk    = (const float*)d_in[5];
    const float* Wv    = (const float*)d_in[6];
    const float* Wp    = (const float*)d_in[7];
    const float* Wout  = (const float*)d_in[8];
    const float* bout  = (const float*)d_in[9];
    float* out = (float*)d_out;

    float *q, *k, *v, *wq, *se, *hid;
    cudaGetSymbolAddress((void**)&q,   g_q);
    cudaGetSymbolAddress((void**)&k,   g_k);
    cudaGetSymbolAddress((void**)&v,   g_v);
    cudaGetSymbolAddress((void**)&wq,  g_wq);
    cudaGetSymbolAddress((void**)&se,  g_se);
    cudaGetSymbolAddress((void**)&hid, g_hid);

    cudaFuncSetAttribute(k_fused,
                         cudaFuncAttributeMaxDynamicSharedMemorySize,
                         FK_SMEM_BYTES);

    // 1. q/k/v projections (q scaled)
    k_gemm_qkv<<<dim3(32, 4, 3), 256>>>(iq, ik, iv, Wq, Wk, Wv, q, k, v);

    // 2. wq + scores_e (merged, single K-tile)
    k_wq_se<<<dim3(32, 8, 24), 256>>>(q, k, Wp, wq, se);

    // 3. fused scores_p + scores_e + softmax + attn@V -> hidden
    k_fused<<<dim3(512, 2), 256, FK_SMEM_BYTES>>>(embed, wq, se, v, hid);

    // 4. out = hidden @ Wout + bout
    k_gemm_out<<<dim3(32, 4, 1), 256>>>(hid, Wout, out, bout);
}

// round 15
// speedup vs baseline: 1.4300x; 1.0369x over previous
#include <cuda_runtime.h>

// RPE MHA, sm_100a. B=2, N=M=512, C=256, H=8, D=32.
// scores_p = embed . wq with wq = Wp-projected q (avoids projecting embed).
// R14 = R13 + packed f32x2 FMA in the score and PV phases (halves FMA-pipe
// issue cost; the fused kernel is issue-bound, not DRAM-bound).

#define SCALE_Q 0.17677669529663687f  // 32^-0.5, folded into q projection

__device__ float g_q[1024 * 256];
__device__ float g_k[1024 * 256];
__device__ float g_v[1024 * 256];
__device__ float g_wq[8 * 1024 * 256];     // [h][bn][c]
__device__ float g_se[16 * 512 * 512];     // [b*8+h][n][m]
__device__ float g_hid[1024 * 256];        // [bn][c]

// fused kernel dynamic smem: ES ring 16384 floats + S 8*520 floats
#define FK_SMEM_BYTES ((16384 + 8 * 520) * 4)

// ---------------------------------------------------------------------------
// packed f32x2 helpers (Blackwell dual-FMA)
// ---------------------------------------------------------------------------
#define FMA2(d, a, b, c) \
    asm("fma.rn.f32x2 %0, %1, %2, %3;" : "=l"(d) : "l"(a), "l"(b), "l"(c))
#define MUL2(d, a, b) \
    asm("mul.rn.f32x2 %0, %1, %2;" : "=l"(d) : "l"(a), "l"(b))
#define UNPACK2(lo, hi, v) \
    asm("mov.b64 {%0, %1}, %2;" : "=f"(lo), "=f"(hi) : "l"(v))
#define PACK2(d, lo, hi) \
    asm("mov.b64 %0, {%1, %2};" : "=l"(d) : "f"(lo), "f"(hi))

// ---------------------------------------------------------------------------
// cp.async helpers
// ---------------------------------------------------------------------------
__device__ __forceinline__ void cp16(float* dst_smem, const float* src)
{
    unsigned d = (unsigned)__cvta_generic_to_shared(dst_smem);
    asm volatile("cp.async.cg.shared.global [%0], [%1], 16;" :: "r"(d), "l"(src));
}
__device__ __forceinline__ void cp_commit()
{
    asm volatile("cp.async.commit_group;");
}
__device__ __forceinline__ void cp_wait3()
{
    asm volatile("cp.async.wait_group 3;");
}

// ---------------------------------------------------------------------------
// 32x64 tiled fp32 GEMM, 256 threads, K-tile 32, register double-buffered.
// BT=false: C = A[m][k] @ B[k][n].  BT=true: C = A[m][k] @ B[n][k].
// ---------------------------------------------------------------------------
template <bool BT>
__device__ __forceinline__ void gemm_body(
    const float* __restrict__ A, int lda,
    const float* __restrict__ B, int ldb,
    float* __restrict__ C, int ldc,
    int N, int K, float scale, const float* __restrict__ bias)
{
    __shared__ float As[32][36];
    __shared__ float Bs[32][68];

    const int tid = threadIdx.x;
    const int m0 = blockIdx.x * 32;
    const int n0 = blockIdx.y * 64;

    const int lr = tid >> 3;
    const int lc = (tid & 7) << 2;
    const int bk = tid >> 4;
    const int bn_ = (tid & 15) << 2;
    const int nr0 = tid >> 3;
    const int nr1 = (tid + 256) >> 3;
    const int nc = (tid & 7) << 2;
    const int ty = tid >> 4;
    const int tx = tid & 15;

    float acc[2][4];
#pragma unroll
    for (int i = 0; i < 2; i++)
#pragma unroll
        for (int j = 0; j < 4; j++) acc[i][j] = 0.0f;

    float4 a4 = *(const float4*)(A + (long)(m0 + lr) * lda + lc);
    float4 t0, t1;
    if (BT) {
        t0 = *(const float4*)(B + (long)(n0 + nr0) * ldb + nc);
        t1 = *(const float4*)(B + (long)(n0 + nr1) * ldb + nc);
    } else {
        t0 = make_float4(0.f, 0.f, 0.f, 0.f);
        t1 = make_float4(0.f, 0.f, 0.f, 0.f);
        if (n0 + bn_ < N) {
            t0 = *(const float4*)(B + (long)bk * ldb + n0 + bn_);
            t1 = *(const float4*)(B + (long)(bk + 16) * ldb + n0 + bn_);
        }
    }

    for (int k0 = 0; k0 < K; k0 += 32) {
        *(float4*)&As[lr][lc] = a4;
        if (BT) {
            Bs[nc + 0][nr0] = t0.x;
            Bs[nc + 1][nr0] = t0.y;
            Bs[nc + 2][nr0] = t0.z;
            Bs[nc + 3][nr0] = t0.w;
            Bs[nc + 0][nr1] = t1.x;
            Bs[nc + 1][nr1] = t1.y;
            Bs[nc + 2][nr1] = t1.z;
            Bs[nc + 3][nr1] = t1.w;
        } else {
            *(float4*)&Bs[bk][bn_]      = t0;
            *(float4*)&Bs[bk + 16][bn_] = t1;
        }
        __syncthreads();

        if (k0 + 32 < K) {
            a4 = *(const float4*)(A + (long)(m0 + lr) * lda + k0 + 32 + lc);
            if (BT) {
                t0 = *(const float4*)(B + (long)(n0 + nr0) * ldb + k0 + 32 + nc);
                t1 = *(const float4*)(B + (long)(n0 + nr1) * ldb + k0 + 32 + nc);
            } else {
                t0 = make_float4(0.f, 0.f, 0.f, 0.f);
                t1 = make_float4(0.f, 0.f, 0.f, 0.f);
                if (n0 + bn_ < N) {
                    t0 = *(const float4*)(B + (long)(k0 + 32 + bk) * ldb + n0 + bn_);
                    t1 = *(const float4*)(B + (long)(k0 + 48 + bk) * ldb + n0 + bn_);
                }
            }
        }

#pragma unroll
        for (int kk = 0; kk < 32; kk++) {
            float a0 = As[ty * 2][kk];
            float a1 = As[ty * 2 + 1][kk];
            float4 bb = *(const float4*)&Bs[kk][tx * 4];
            acc[0][0] += a0 * bb.x;  acc[0][1] += a0 * bb.y;
            acc[0][2] += a0 * bb.z;  acc[0][3] += a0 * bb.w;
            acc[1][0] += a1 * bb.x;  acc[1][1] += a1 * bb.y;
            acc[1][2] += a1 * bb.z;  acc[1][3] += a1 * bb.w;
        }
        __syncthreads();
    }

#pragma unroll
    for (int i = 0; i < 2; i++) {
#pragma unroll
        for (int j = 0; j < 4; j++) {
            int nn = n0 + tx * 4 + j;
            if (nn < N) {
                float val = acc[i][j] * scale;
                if (bias) val += bias[nn];
                C[(long)(m0 + ty * 2 + i) * ldc + nn] = val;
            }
        }
    }
}

// q/k/v projections batched over grid.z
__global__ void __launch_bounds__(256) k_gemm_qkv(
    const float* Aq, const float* Ak, const float* Av,
    const float* Bq, const float* Bk, const float* Bv,
    float* Cq, float* Ck, float* Cv)
{
    int z = blockIdx.z;
    const float* A = (z == 0) ? Aq : (z == 1) ? Ak : Av;
    const float* B = (z == 0) ? Bq : (z == 1) ? Bk : Bv;
    float*       C = (z == 0) ? Cq : (z == 1) ? Ck : Cv;
    gemm_body<false>(A, 256, B, 256, C, 256, 256, 256,
                     (z == 0) ? SCALE_Q : 1.0f, nullptr);
}

// Combined wq + scores_e (K=32 -> single K-tile, no loop). grid (32, 8, 24).
__global__ void __launch_bounds__(256) k_wq_se(
    const float* __restrict__ q, const float* __restrict__ kmat,
    const float* __restrict__ Wp,
    float* __restrict__ wqo, float* __restrict__ seo)
{
    int z = blockIdx.z;
    if (z < 8) {
        if (blockIdx.y >= 4) return;
        gemm_body<true>(q + z * 32, 256,
                        Wp + z * 32, 256,
                        wqo + (long)z * 262144, 256,
                        256, 32, 1.0f, nullptr);
    } else {
        if (blockIdx.x >= 16) return;
        int zz = z - 8, bb = zz >> 3, hh = zz & 7;
        gemm_body<true>(q + (long)bb * 131072 + hh * 32, 256,
                        kmat + (long)bb * 131072 + hh * 32, 256,
                        seo + (long)zz * 262144, 512,
                        512, 32, 1.0f, nullptr);
    }
}

// out = hidden @ Wout + bout
__global__ void __launch_bounds__(256) k_gemm_out(
    const float* A, const float* B, float* C, const float* bias)
{
    gemm_body<false>(A, 256, B, 256, C, 256, 256, 256, 1.0f, bias);
}

// ---------------------------------------------------------------------------
// Fused scores_p + scores_e(add) + softmax + attn@V -> hidden.
// CTA per (b,n), 256 threads. Warp w owns rows m in [64w, 64w+64) for the
// score phase, head w for softmax + PV. cp.async 4-stage x 2-row smem ring.
// Score math in packed f32x2 (dual-FMA).
// ---------------------------------------------------------------------------
__device__ __forceinline__ float reduce8(const float* a, int l)
{
    float r[4];
#pragma unroll
    for (int j = 0; j < 4; j++) {
        float send = (l & 1) ? a[j] : a[j + 4];
        float keep = (l & 1) ? a[j + 4] : a[j];
        r[j] = keep + __shfl_xor_sync(0xFFFFFFFFu, send, 1);
    }
    float r2[2];
#pragma unroll
    for (int j = 0; j < 2; j++) {
        float send = (l & 2) ? r[j] : r[j + 2];
        float keep = (l & 2) ? r[j + 2] : r[j];
        r2[j] = keep + __shfl_xor_sync(0xFFFFFFFFu, send, 2);
    }
    float send = (l & 4) ? r2[0] : r2[1];
    float keep = (l & 4) ? r2[1] : r2[0];
    float s = keep + __shfl_xor_sync(0xFFFFFFFFu, send, 4);
    s += __shfl_xor_sync(0xFFFFFFFFu, s, 8);
    s += __shfl_xor_sync(0xFFFFFFFFu, s, 16);
    return s;
}

// scores for 2 rows; all operands packed f32x2 (ulonglong2 = 2 channel-pairs)
__device__ __forceinline__ void score2(
    ulonglong2 X0, ulonglong2 X1, ulonglong2 Y0, ulonglong2 Y1,
    const ulonglong2* w0, const ulonglong2* w1,
    float* S, int mbase, int hlane, int l)
{
    float a[8], c[8];
#pragma unroll
    for (int h = 0; h < 8; h++) {
        unsigned long long ta, tc;
        MUL2(ta, X0.x, w0[h].x);
        FMA2(ta, X0.y, w0[h].y, ta);
        FMA2(ta, X1.x, w1[h].x, ta);
        FMA2(ta, X1.y, w1[h].y, ta);
        float lo, hi;
        UNPACK2(lo, hi, ta);
        a[h] = lo + hi;
        MUL2(tc, Y0.x, w0[h].x);
        FMA2(tc, Y0.y, w0[h].y, tc);
        FMA2(tc, Y1.x, w1[h].x, tc);
        FMA2(tc, Y1.y, w1[h].y, tc);
        UNPACK2(lo, hi, tc);
        c[h] = lo + hi;
    }
    float sA = reduce8(a, l);
    float sB = reduce8(c, l);
    if (l < 8) {
        S[hlane * 520 + mbase]     = sA;
        S[hlane * 520 + mbase + 1] = sB;
    }
}

__global__ void __launch_bounds__(256, 2) k_fused(
    const float* __restrict__ embed,  // [b][n][m][c]
    const float* __restrict__ wq,     // [h][bn][c]
    const float* __restrict__ se,     // [b*8+h][n][m]
    const float* __restrict__ vmat,   // [b*512+m][c]
    float* __restrict__ hid)          // [bn][c]
{
    extern __shared__ float sm[];
    // ES ring: [8 warps][4 stages][2 rows][256 floats] = 16384 floats (64KB)
    float* S = sm + 16384;

    const int n = blockIdx.x;
    const int b = blockIdx.y;
    const int t = threadIdx.x;
    const int w = t >> 5, l = t & 31;
    const long bn = (long)b * 512 + n;

    // per-lane wq slice, loaded directly as packed pairs
    ulonglong2 w0p[8], w1p[8];
#pragma unroll
    for (int h = 0; h < 8; h++) {
        const float* wp = wq + ((long)h * 1024 + bn) * 256;
        w0p[h] = *(const ulonglong2*)(wp + 4 * l);
        w1p[h] = *(const ulonglong2*)(wp + 128 + 4 * l);
    }
    const int hlane = ((l & 1) << 2) | (l & 2) | ((l & 4) >> 2);

    // warp's 64 embed rows; lane offset folded in
    const float* Eg = embed + bn * 131072L + (long)(w << 6) * 256 + l * 4;
    float* ESw = sm + (w << 11) + l * 4;    // warp ring base + lane offset

    // prime 4 stages (stage s = rows 2s, 2s+1 = 512 floats)
#pragma unroll
    for (int s = 0; s < 4; s++) {
        const float* src = Eg + s * 512;
        float* d = ESw + s * 512;
        cp16(d,       src);
        cp16(d + 128, src + 128);
        cp16(d + 256, src + 256);
        cp16(d + 384, src + 384);
        cp_commit();
    }

#pragma unroll 4
    for (int i = 0; i < 32; i++) {
        const int slot = i & 3;
        cp_wait3();                       // stage i complete
        const float* Ap = ESw + slot * 512;
        ulonglong2 x0 = *(const ulonglong2*)(Ap);
        ulonglong2 x1 = *(const ulonglong2*)(Ap + 128);
        ulonglong2 y0 = *(const ulonglong2*)(Ap + 256);
        ulonglong2 y1 = *(const ulonglong2*)(Ap + 384);
        if (i + 4 < 32) {                 // refill slot for phase i+4
            const float* src = Eg + (i + 4) * 512;
            float* d = ESw + slot * 512;
            cp16(d,       src);
            cp16(d + 128, src + 128);
            cp16(d + 256, src + 256);
            cp16(d + 384, src + 384);
        }
        cp_commit();                      // keep group count aligned
        score2(x0, x1, y0, y1, w0p, w1p, S, (w << 6) + 2 * i, hlane, l);
    }
    __syncthreads();

    // softmax: warp w -> head w; lane owns m = {64j + 2l, +1}, j = 0..7
    const float* Sr  = S + w * 520;
    const float* ser = se + (long)(b * 8 + w) * 262144 + (long)n * 512;
    float v[16];
    float mx = -3.0e38f;
#pragma unroll
    for (int j = 0; j < 8; j++) {
        float2 sv = *(const float2*)(Sr  + j * 64 + l * 2);
        float2 ev = *(const float2*)(ser + j * 64 + l * 2);
        v[2 * j]     = sv.x + ev.x;
        v[2 * j + 1] = sv.y + ev.y;
        mx = fmaxf(mx, fmaxf(v[2 * j], v[2 * j + 1]));
    }
#pragma unroll
    for (int off = 16; off > 0; off >>= 1)
        mx = fmaxf(mx, __shfl_xor_sync(0xFFFFFFFFu, mx, off));

    float sum = 0.f;
#pragma unroll
    for (int j = 0; j < 16; j++) {
        v[j] = __expf(v[j] - mx);
        sum += v[j];
    }
#pragma unroll
    for (int off = 16; off > 0; off >>= 1)
        sum += __shfl_xor_sync(0xFFFFFFFFu, sum, off);

    const float inv = 1.0f / sum;
#pragma unroll
    for (int j = 0; j < 16; j++) v[j] *= inv;

    // PV: hid[w*32 + d] = sum_m v[m] * V[b*512+m][w*32+d]  (packed f32x2)
    const int rg = l >> 3;
    const float* Vb = vmat + (long)b * 131072 + w * 32 + (l & 7) * 4;
    unsigned long long accA, accB;
    {
        float z = 0.f;
        PACK2(accA, z, z);
        PACK2(accB, z, z);
    }
#pragma unroll
    for (int j = 0; j < 8; j++) {
        float s0v = v[2 * j], s1v = v[2 * j + 1];
#pragma unroll
        for (int g = 0; g < 16; g++) {
            int r = j * 64 + g * 4 + rg;
            ulonglong2 V2 = *(const ulonglong2*)(Vb + (long)r * 256);
            int src = g * 2 + (rg >> 1);
            float e0 = __shfl_sync(0xFFFFFFFFu, s0v, src);
            float e1 = __shfl_sync(0xFFFFFFFFu, s1v, src);
            float av = (rg & 1) ? e1 : e0;
            unsigned long long avp;
            PACK2(avp, av, av);
            FMA2(accA, V2.x, avp, accA);
            FMA2(accB, V2.y, avp, accB);
        }
    }
    float4 acc;
    UNPACK2(acc.x, acc.y, accA);
    UNPACK2(acc.z, acc.w, accB);
#pragma unroll
    for (int off = 8; off <= 16; off <<= 1) {
        acc.x += __shfl_xor_sync(0xFFFFFFFFu, acc.x, off);
        acc.y += __shfl_xor_sync(0xFFFFFFFFu, acc.y, off);
        acc.z += __shfl_xor_sync(0xFFFFFFFFu, acc.z, off);
        acc.w += __shfl_xor_sync(0xFFFFFFFFu, acc.w, off);
    }
    if (l < 8)
        *(float4*)(hid + bn * 256 + w * 32 + l * 4) = acc;
}

extern "C" void kernel_launch(void* const* d_in, const int* in_sizes, int n_in,
                              void* d_out, int out_size)
{
    const float* iq    = (const float*)d_in[0];
    const float* ik    = (const float*)d_in[1];
    const float* iv    = (const float*)d_in[2];
    const float* embed = (const float*)d_in[3];
    const float* Wq    = (const float*)d_in[4];
    const float* Wk    = (const float*)d_in[5];
    const float* Wv    = (const float*)d_in[6];
    const float* Wp    = (const float*)d_in[7];
    const float* Wout  = (const float*)d_in[8];
    const float* bout  = (const float*)d_in[9];
    float* out = (float*)d_out;

    float *q, *k, *v, *wq, *se, *hid;
    cudaGetSymbolAddress((void**)&q,   g_q);
    cudaGetSymbolAddress((void**)&k,   g_k);
    cudaGetSymbolAddress((void**)&v,   g_v);
    cudaGetSymbolAddress((void**)&wq,  g_wq);
    cudaGetSymbolAddress((void**)&se,  g_se);
    cudaGetSymbolAddress((void**)&hid, g_hid);

    cudaFuncSetAttribute(k_fused,
                         cudaFuncAttributeMaxDynamicSharedMemorySize,
                         FK_SMEM_BYTES);

    // 1. q/k/v projections (q scaled)
    k_gemm_qkv<<<dim3(32, 4, 3), 256>>>(iq, ik, iv, Wq, Wk, Wv, q, k, v);

    // 2. wq + scores_e (merged, single K-tile)
    k_wq_se<<<dim3(32, 8, 24), 256>>>(q, k, Wp, wq, se);

    // 3. fused scores_p + scores_e + softmax + attn@V -> hidden
    k_fused<<<dim3(512, 2), 256, FK_SMEM_BYTES>>>(embed, wq, se, v, hid);

    // 4. out = hidden @ Wout + bout
    k_gemm_out<<<dim3(32, 4, 1), 256>>>(hid, Wout, out, bout);
}